// round 2
// baseline (speedup 1.0000x reference)
#include <cuda_runtime.h>

#define NN 50000
#define EE 1600000
#define F  128
#define H  4
#define D  32
#define HD 128

// Scratch (allocation-free rule: __device__ globals)
__device__ float g_h[NN * HD];          // projected features, 25.6 MB (L2-resident)
__device__ float g_es[NN * H];          // per-node source logits
__device__ float g_ed[NN * H];          // per-node dest logits
__device__ int   g_count[NN];           // in-degree histogram
__device__ int   g_rowstart[NN + 1];    // CSR row offsets (by dst)
__device__ int   g_cursor[NN];          // scatter cursors
__device__ int   g_srcsorted[EE];       // src node per edge, grouped by dst
__device__ int   g_is64;                // 1 if edge arrays are int64, 0 if int32

// ---------------------------------------------------------------------------
// K-1: detect edge dtype. If the buffer is really int64, the first 8 values
// are all valid node ids. If it's int32 data read as int64, each read packs
// two random ids -> astronomically unlikely to all be < NN.
// ---------------------------------------------------------------------------
__global__ void detect_kernel(const void* edges) {
    const long long* p = (const long long*)edges;
    int ok = 1;
    #pragma unroll
    for (int i = 0; i < 8; i++) {
        long long v = p[i];
        if (v < 0 || v >= NN) ok = 0;
    }
    g_is64 = ok;
}

__device__ __forceinline__ int edge_at(const void* edges, int i) {
    if (g_is64) return (int)((const long long*)edges)[i];
    return ((const int*)edges)[i];
}

// ---------------------------------------------------------------------------
// K0: zero the histogram (graph replays re-run everything)
// ---------------------------------------------------------------------------
__global__ void zero_kernel(int n) {
    int i = blockIdx.x * blockDim.x + threadIdx.x;
    if (i < n) g_count[i] = 0;
}

// ---------------------------------------------------------------------------
// K1: h = x @ W.  128x128 output tile per block, 8x8 register tile per thread,
// K chunked by 32 with x stored transposed in smem (conflict-light).
// ---------------------------------------------------------------------------
__global__ __launch_bounds__(256) void gemm_kernel(
    const float* __restrict__ x, const float* __restrict__ W, int n)
{
    __shared__ float xs[32][132];   // [k][m], padded
    __shared__ float ws[32][128];   // [k][n]

    int tid = threadIdx.x;
    int rowBase = blockIdx.x * 128;
    int ty = tid >> 4, tx = tid & 15;
    int m0 = ty * 8, n0 = tx * 8;

    float acc[8][8];
    #pragma unroll
    for (int i = 0; i < 8; i++)
        #pragma unroll
        for (int j = 0; j < 8; j++) acc[i][j] = 0.f;

    const float4* x4 = (const float4*)x;
    const float4* W4 = (const float4*)W;

    for (int kc = 0; kc < 4; ++kc) {
        #pragma unroll
        for (int i = 0; i < 4; ++i) {
            int idx = i * 256 + tid;
            int row = idx >> 3;
            int kq  = idx & 7;
            float4 v = make_float4(0.f, 0.f, 0.f, 0.f);
            if (rowBase + row < n) v = x4[(size_t)(rowBase + row) * 32 + kc * 8 + kq];
            xs[kq * 4 + 0][row] = v.x;
            xs[kq * 4 + 1][row] = v.y;
            xs[kq * 4 + 2][row] = v.z;
            xs[kq * 4 + 3][row] = v.w;
        }
        #pragma unroll
        for (int i = 0; i < 4; ++i) {
            int idx = i * 256 + tid;
            int kr = idx >> 5;
            int nq = idx & 31;
            float4 v = W4[(size_t)(kc * 32 + kr) * 32 + nq];
            *(float4*)&ws[kr][nq * 4] = v;
        }
        __syncthreads();

        #pragma unroll
        for (int k = 0; k < 32; ++k) {
            float4 a0 = *(const float4*)&xs[k][m0];
            float4 a1 = *(const float4*)&xs[k][m0 + 4];
            float4 b0 = *(const float4*)&ws[k][n0];
            float4 b1 = *(const float4*)&ws[k][n0 + 4];
            float a[8] = {a0.x, a0.y, a0.z, a0.w, a1.x, a1.y, a1.z, a1.w};
            float b[8] = {b0.x, b0.y, b0.z, b0.w, b1.x, b1.y, b1.z, b1.w};
            #pragma unroll
            for (int i = 0; i < 8; i++)
                #pragma unroll
                for (int j = 0; j < 8; j++)
                    acc[i][j] = fmaf(a[i], b[j], acc[i][j]);
        }
        __syncthreads();
    }

    #pragma unroll
    for (int i = 0; i < 8; i++) {
        int row = rowBase + m0 + i;
        if (row < n) {
            float4 v0 = make_float4(acc[i][0], acc[i][1], acc[i][2], acc[i][3]);
            float4 v1 = make_float4(acc[i][4], acc[i][5], acc[i][6], acc[i][7]);
            *(float4*)&g_h[(size_t)row * HD + n0]     = v0;
            *(float4*)&g_h[(size_t)row * HD + n0 + 4] = v1;
        }
    }
}

// ---------------------------------------------------------------------------
// K2: per-node attention logits. One warp per node; lane l covers features
// [4l, 4l+4) -> head = l/8; reduction within 8-lane head groups.
// ---------------------------------------------------------------------------
__global__ void logits_kernel(const float* __restrict__ a_src,
                              const float* __restrict__ a_dst, int n)
{
    int gw = (blockIdx.x * blockDim.x + threadIdx.x) >> 5;
    int lane = threadIdx.x & 31;
    if (gw >= n) return;
    int hd = lane >> 3;
    int sub = lane & 7;

    float4 hv = *(const float4*)&g_h[(size_t)gw * HD + lane * 4];
    float4 as = *(const float4*)&a_src[hd * D + sub * 4];
    float4 ad = *(const float4*)&a_dst[hd * D + sub * 4];

    float s = hv.x * as.x + hv.y * as.y + hv.z * as.z + hv.w * as.w;
    float d = hv.x * ad.x + hv.y * ad.y + hv.z * ad.z + hv.w * ad.w;

    s += __shfl_down_sync(0xffffffffu, s, 4, 8);
    s += __shfl_down_sync(0xffffffffu, s, 2, 8);
    s += __shfl_down_sync(0xffffffffu, s, 1, 8);
    d += __shfl_down_sync(0xffffffffu, d, 4, 8);
    d += __shfl_down_sync(0xffffffffu, d, 2, 8);
    d += __shfl_down_sync(0xffffffffu, d, 1, 8);

    if (sub == 0) {
        g_es[gw * H + hd] = s;
        g_ed[gw * H + hd] = d;
    }
}

// ---------------------------------------------------------------------------
// K3: in-degree histogram
// ---------------------------------------------------------------------------
__global__ void hist_kernel(const void* __restrict__ edge_dst, int e) {
    int i = blockIdx.x * blockDim.x + threadIdx.x;
    if (i < e) atomicAdd(&g_count[edge_at(edge_dst, i)], 1);
}

// ---------------------------------------------------------------------------
// K4: single-block exclusive scan over counts -> rowstart + cursors
// ---------------------------------------------------------------------------
__global__ void scan_kernel(int n) {
    __shared__ int part[1024];
    int t = threadIdx.x;
    int per = (n + 1023) / 1024;
    int s = t * per;
    int e = min(s + per, n);

    int sum = 0;
    for (int i = s; i < e; i++) sum += g_count[i];
    part[t] = sum;
    __syncthreads();

    for (int off = 1; off < 1024; off <<= 1) {
        int v = (t >= off) ? part[t - off] : 0;
        __syncthreads();
        part[t] += v;
        __syncthreads();
    }

    int base = (t == 0) ? 0 : part[t - 1];
    for (int i = s; i < e; i++) {
        g_rowstart[i] = base;
        g_cursor[i]   = base;
        base += g_count[i];
    }
    if (t == 1023) g_rowstart[n] = part[1023];
}

// ---------------------------------------------------------------------------
// K5: scatter edges into dst-grouped order
// ---------------------------------------------------------------------------
__global__ void scatter_kernel(const void* __restrict__ edge_src,
                               const void* __restrict__ edge_dst, int e)
{
    int i = blockIdx.x * blockDim.x + threadIdx.x;
    if (i >= e) return;
    int dst = edge_at(edge_dst, i);
    int pos = atomicAdd(&g_cursor[dst], 1);
    g_srcsorted[pos] = edge_at(edge_src, i);
}

// ---------------------------------------------------------------------------
// K6: aggregation. One warp per destination node, register accumulators,
// no output atomics. Softmax without max-subtraction (logit std ~0.8, safe).
// ---------------------------------------------------------------------------
__global__ void agg_kernel(const float* __restrict__ bias,
                           float* __restrict__ out, int n)
{
    int gw = (blockIdx.x * blockDim.x + threadIdx.x) >> 5;
    int lane = threadIdx.x & 31;
    if (gw >= n) return;
    int hd = lane >> 3;

    float edv = g_ed[gw * H + hd];
    int start = g_rowstart[gw];
    int end   = g_rowstart[gw + 1];

    float4 acc = make_float4(0.f, 0.f, 0.f, 0.f);
    float denom = 0.f;
    const float4* h4 = (const float4*)g_h;

    #pragma unroll 4
    for (int i = start; i < end; ++i) {
        int src = g_srcsorted[i];
        float ev = g_es[src * H + hd] + edv;
        ev = fmaxf(ev, 0.2f * ev);          // LeakyReLU(0.2)
        float al = __expf(ev);
        denom += al;
        float4 hv = h4[(size_t)src * 32 + lane];
        acc.x = fmaf(al, hv.x, acc.x);
        acc.y = fmaf(al, hv.y, acc.y);
        acc.z = fmaf(al, hv.z, acc.z);
        acc.w = fmaf(al, hv.w, acc.w);
    }

    float inv = denom > 0.f ? 1.0f / denom : 0.f;
    float4 bv = ((const float4*)bias)[lane];
    float4 o;
    o.x = fmaf(acc.x, inv, bv.x);
    o.y = fmaf(acc.y, inv, bv.y);
    o.z = fmaf(acc.z, inv, bv.z);
    o.w = fmaf(acc.w, inv, bv.w);
    ((float4*)out)[(size_t)gw * 32 + lane] = o;
}

// ---------------------------------------------------------------------------
extern "C" void kernel_launch(void* const* d_in, const int* in_sizes, int n_in,
                              void* d_out, int out_size)
{
    const float* x      = (const float*)d_in[0];
    const float* W      = (const float*)d_in[1];
    const float* a_src  = (const float*)d_in[2];
    const float* a_dst  = (const float*)d_in[3];
    const float* bias   = (const float*)d_in[4];
    const void*  esrc   = d_in[5];
    const void*  edst   = d_in[6];
    float* out = (float*)d_out;

    int n = in_sizes[0] / F;     // 50000
    int e = in_sizes[5];         // 1600000

    detect_kernel<<<1, 1>>>(edst);
    zero_kernel<<<(n + 255) / 256, 256>>>(n);
    gemm_kernel<<<(n + 127) / 128, 256>>>(x, W, n);
    logits_kernel<<<(n * 32 + 255) / 256, 256>>>(a_src, a_dst, n);
    hist_kernel<<<(e + 255) / 256, 256>>>(edst, e);
    scan_kernel<<<1, 1024>>>(n);
    scatter_kernel<<<(e + 255) / 256, 256>>>(esrc, edst, e);
    agg_kernel<<<(n * 32 + 255) / 256, 256>>>(bias, out, n);
}

// round 3
// speedup vs baseline: 1.0851x; 1.0851x over previous
#include <cuda_runtime.h>
#include <cuda_fp16.h>

#define NN 50000
#define EE 1600000
#define F  128
#define H  4
#define D  32
#define HD 128

// Scratch (allocation-free rule: __device__ globals)
__device__ __half g_h[NN * HD];         // projected features fp16, 12.8 MB (L2-resident)
__device__ float g_es[NN * H];          // per-node source logits
__device__ float g_ed[NN * H];          // per-node dest logits
__device__ int   g_count[NN];           // in-degree histogram
__device__ int   g_rowstart[NN + 1];    // CSR row offsets (by dst)
__device__ int   g_cursor[NN];          // scatter cursors
__device__ int   g_srcsorted[EE];       // src node per edge, grouped by dst
__device__ int   g_is64;                // 1 if edge arrays are int64, 0 if int32

// ---------------------------------------------------------------------------
// K-1: detect edge dtype (int64 vs int32).
// ---------------------------------------------------------------------------
__global__ void detect_kernel(const void* edges) {
    const long long* p = (const long long*)edges;
    int ok = 1;
    #pragma unroll
    for (int i = 0; i < 8; i++) {
        long long v = p[i];
        if (v < 0 || v >= NN) ok = 0;
    }
    g_is64 = ok;
}

__device__ __forceinline__ int edge_at(const void* edges, int i) {
    if (g_is64) return (int)((const long long*)edges)[i];
    return ((const int*)edges)[i];
}

// ---------------------------------------------------------------------------
// K0: zero the histogram
// ---------------------------------------------------------------------------
__global__ void zero_kernel(int n) {
    int i = blockIdx.x * blockDim.x + threadIdx.x;
    if (i < n) g_count[i] = 0;
}

// ---------------------------------------------------------------------------
// K1: h = x @ W, written as fp16. 128x128 tile/block, 8x8 reg tile/thread.
// ---------------------------------------------------------------------------
__global__ __launch_bounds__(256) void gemm_kernel(
    const float* __restrict__ x, const float* __restrict__ W, int n)
{
    __shared__ float xs[32][132];   // [k][m], padded
    __shared__ float ws[32][128];   // [k][n]

    int tid = threadIdx.x;
    int rowBase = blockIdx.x * 128;
    int ty = tid >> 4, tx = tid & 15;
    int m0 = ty * 8, n0 = tx * 8;

    float acc[8][8];
    #pragma unroll
    for (int i = 0; i < 8; i++)
        #pragma unroll
        for (int j = 0; j < 8; j++) acc[i][j] = 0.f;

    const float4* x4 = (const float4*)x;
    const float4* W4 = (const float4*)W;

    for (int kc = 0; kc < 4; ++kc) {
        #pragma unroll
        for (int i = 0; i < 4; ++i) {
            int idx = i * 256 + tid;
            int row = idx >> 3;
            int kq  = idx & 7;
            float4 v = make_float4(0.f, 0.f, 0.f, 0.f);
            if (rowBase + row < n) v = x4[(size_t)(rowBase + row) * 32 + kc * 8 + kq];
            xs[kq * 4 + 0][row] = v.x;
            xs[kq * 4 + 1][row] = v.y;
            xs[kq * 4 + 2][row] = v.z;
            xs[kq * 4 + 3][row] = v.w;
        }
        #pragma unroll
        for (int i = 0; i < 4; ++i) {
            int idx = i * 256 + tid;
            int kr = idx >> 5;
            int nq = idx & 31;
            float4 v = W4[(size_t)(kc * 32 + kr) * 32 + nq];
            *(float4*)&ws[kr][nq * 4] = v;
        }
        __syncthreads();

        #pragma unroll
        for (int k = 0; k < 32; ++k) {
            float4 a0 = *(const float4*)&xs[k][m0];
            float4 a1 = *(const float4*)&xs[k][m0 + 4];
            float4 b0 = *(const float4*)&ws[k][n0];
            float4 b1 = *(const float4*)&ws[k][n0 + 4];
            float a[8] = {a0.x, a0.y, a0.z, a0.w, a1.x, a1.y, a1.z, a1.w};
            float b[8] = {b0.x, b0.y, b0.z, b0.w, b1.x, b1.y, b1.z, b1.w};
            #pragma unroll
            for (int i = 0; i < 8; i++)
                #pragma unroll
                for (int j = 0; j < 8; j++)
                    acc[i][j] = fmaf(a[i], b[j], acc[i][j]);
        }
        __syncthreads();
    }

    #pragma unroll
    for (int i = 0; i < 8; i++) {
        int row = rowBase + m0 + i;
        if (row < n) {
            union { __half2 h2[4]; uint4 u; } pk;
            pk.h2[0] = __floats2half2_rn(acc[i][0], acc[i][1]);
            pk.h2[1] = __floats2half2_rn(acc[i][2], acc[i][3]);
            pk.h2[2] = __floats2half2_rn(acc[i][4], acc[i][5]);
            pk.h2[3] = __floats2half2_rn(acc[i][6], acc[i][7]);
            *(uint4*)&g_h[(size_t)row * HD + n0] = pk.u;
        }
    }
}

// ---------------------------------------------------------------------------
// K2: per-node attention logits from fp16 h. One warp per node.
// lane l covers features [4l,4l+4) -> head = l/8; reduce within 8-lane groups.
// ---------------------------------------------------------------------------
__global__ void logits_kernel(const float* __restrict__ a_src,
                              const float* __restrict__ a_dst, int n)
{
    int gw = (blockIdx.x * blockDim.x + threadIdx.x) >> 5;
    int lane = threadIdx.x & 31;
    if (gw >= n) return;
    int hd = lane >> 3;
    int sub = lane & 7;

    uint2 raw = ((const uint2*)g_h)[(size_t)gw * 32 + lane];
    float2 f0 = __half22float2(*(__half2*)&raw.x);
    float2 f1 = __half22float2(*(__half2*)&raw.y);

    float4 as = *(const float4*)&a_src[hd * D + sub * 4];
    float4 ad = *(const float4*)&a_dst[hd * D + sub * 4];

    float s = f0.x * as.x + f0.y * as.y + f1.x * as.z + f1.y * as.w;
    float d = f0.x * ad.x + f0.y * ad.y + f1.x * ad.z + f1.y * ad.w;

    s += __shfl_down_sync(0xffffffffu, s, 4, 8);
    s += __shfl_down_sync(0xffffffffu, s, 2, 8);
    s += __shfl_down_sync(0xffffffffu, s, 1, 8);
    d += __shfl_down_sync(0xffffffffu, d, 4, 8);
    d += __shfl_down_sync(0xffffffffu, d, 2, 8);
    d += __shfl_down_sync(0xffffffffu, d, 1, 8);

    if (sub == 0) {
        g_es[gw * H + hd] = s;
        g_ed[gw * H + hd] = d;
    }
}

// ---------------------------------------------------------------------------
// K3: in-degree histogram
// ---------------------------------------------------------------------------
__global__ void hist_kernel(const void* __restrict__ edge_dst, int e) {
    int i = blockIdx.x * blockDim.x + threadIdx.x;
    if (i < e) atomicAdd(&g_count[edge_at(edge_dst, i)], 1);
}

// ---------------------------------------------------------------------------
// K4: single-block exclusive scan over counts -> rowstart + cursors
// ---------------------------------------------------------------------------
__global__ void scan_kernel(int n) {
    __shared__ int part[1024];
    int t = threadIdx.x;
    int per = (n + 1023) / 1024;
    int s = t * per;
    int e = min(s + per, n);

    int sum = 0;
    for (int i = s; i < e; i++) sum += g_count[i];
    part[t] = sum;
    __syncthreads();

    for (int off = 1; off < 1024; off <<= 1) {
        int v = (t >= off) ? part[t - off] : 0;
        __syncthreads();
        part[t] += v;
        __syncthreads();
    }

    int base = (t == 0) ? 0 : part[t - 1];
    for (int i = s; i < e; i++) {
        g_rowstart[i] = base;
        g_cursor[i]   = base;
        base += g_count[i];
    }
    if (t == 1023) g_rowstart[n] = part[1023];
}

// ---------------------------------------------------------------------------
// K5: scatter edges into dst-grouped order
// ---------------------------------------------------------------------------
__global__ void scatter_kernel(const void* __restrict__ edge_src,
                               const void* __restrict__ edge_dst, int e)
{
    int i = blockIdx.x * blockDim.x + threadIdx.x;
    if (i >= e) return;
    int dst = edge_at(edge_dst, i);
    int pos = atomicAdd(&g_cursor[dst], 1);
    g_srcsorted[pos] = edge_at(edge_src, i);
}

// ---------------------------------------------------------------------------
// K6: aggregation. One warp per destination node, fp32 accumulators over
// fp16 gathered rows, no output atomics.
// ---------------------------------------------------------------------------
__global__ void agg_kernel(const float* __restrict__ bias,
                           float* __restrict__ out, int n)
{
    int gw = (blockIdx.x * blockDim.x + threadIdx.x) >> 5;
    int lane = threadIdx.x & 31;
    if (gw >= n) return;
    int hd = lane >> 3;

    float edv = g_ed[gw * H + hd];
    int start = g_rowstart[gw];
    int end   = g_rowstart[gw + 1];

    float4 acc = make_float4(0.f, 0.f, 0.f, 0.f);
    float denom = 0.f;
    const uint2* h2 = (const uint2*)g_h;

    #pragma unroll 4
    for (int i = start; i < end; ++i) {
        int src = g_srcsorted[i];
        float ev = g_es[src * H + hd] + edv;
        ev = fmaxf(ev, 0.2f * ev);          // LeakyReLU(0.2)
        float al = __expf(ev);
        denom += al;
        uint2 raw = h2[(size_t)src * 32 + lane];
        float2 f0 = __half22float2(*(__half2*)&raw.x);
        float2 f1 = __half22float2(*(__half2*)&raw.y);
        acc.x = fmaf(al, f0.x, acc.x);
        acc.y = fmaf(al, f0.y, acc.y);
        acc.z = fmaf(al, f1.x, acc.z);
        acc.w = fmaf(al, f1.y, acc.w);
    }

    float inv = denom > 0.f ? 1.0f / denom : 0.f;
    float4 bv = ((const float4*)bias)[lane];
    float4 o;
    o.x = fmaf(acc.x, inv, bv.x);
    o.y = fmaf(acc.y, inv, bv.y);
    o.z = fmaf(acc.z, inv, bv.z);
    o.w = fmaf(acc.w, inv, bv.w);
    ((float4*)out)[(size_t)gw * 32 + lane] = o;
}

// ---------------------------------------------------------------------------
extern "C" void kernel_launch(void* const* d_in, const int* in_sizes, int n_in,
                              void* d_out, int out_size)
{
    const float* x      = (const float*)d_in[0];
    const float* W      = (const float*)d_in[1];
    const float* a_src  = (const float*)d_in[2];
    const float* a_dst  = (const float*)d_in[3];
    const float* bias   = (const float*)d_in[4];
    const void*  esrc   = d_in[5];
    const void*  edst   = d_in[6];
    float* out = (float*)d_out;

    int n = in_sizes[0] / F;     // 50000
    int e = in_sizes[5];         // 1600000

    detect_kernel<<<1, 1>>>(edst);
    zero_kernel<<<(n + 255) / 256, 256>>>(n);
    gemm_kernel<<<(n + 127) / 128, 256>>>(x, W, n);
    logits_kernel<<<(n * 32 + 255) / 256, 256>>>(a_src, a_dst, n);
    hist_kernel<<<(e + 255) / 256, 256>>>(edst, e);
    scan_kernel<<<1, 1024>>>(n);
    scatter_kernel<<<(e + 255) / 256, 256>>>(esrc, edst, e);
    agg_kernel<<<(n * 32 + 255) / 256, 256>>>(bias, out, n);
}

// round 4
// speedup vs baseline: 1.1751x; 1.0830x over previous
#include <cuda_runtime.h>
#include <cuda_fp16.h>

#define NN 50000
#define EE 1600000
#define F  128
#define H  4
#define D  32
#define HD 128

// Scratch (allocation-free rule: __device__ globals)
__device__ __half g_h[NN * HD];         // projected features fp16, 12.8 MB (L2-resident)
__device__ float g_es[NN * H];          // per-node source logits
__device__ float g_ed[NN * H];          // per-node dest logits
__device__ int   g_count[NN];           // in-degree histogram
__device__ int   g_rowstart[NN + 1];    // CSR row offsets (by dst)
__device__ int   g_cursor[NN];          // scatter cursors
__device__ int   g_srcsorted[EE];       // src node per edge, grouped by dst
__device__ int   g_is64;                // 1 if edge arrays are int64, 0 if int32

__device__ __forceinline__ int edge_at(const void* edges, int i) {
    if (g_is64) return (int)((const long long*)edges)[i];
    return ((const int*)edges)[i];
}

// ---------------------------------------------------------------------------
// K0: zero the histogram + detect edge dtype (block 0 thread 0)
// ---------------------------------------------------------------------------
__global__ void zero_kernel(int n, const void* edges) {
    int i = blockIdx.x * blockDim.x + threadIdx.x;
    if (i < n) g_count[i] = 0;
    if (i == 0) {
        const long long* p = (const long long*)edges;
        int ok = 1;
        #pragma unroll
        for (int q = 0; q < 8; q++) {
            long long v = p[q];
            if (v < 0 || v >= NN) ok = 0;
        }
        g_is64 = ok;
    }
}

// ---------------------------------------------------------------------------
// K1: h = x @ W via HMMA (mma.sync m16n8k16, fp16 in, fp32 accum).
// Block = 128 threads (4 warps), tile 64 rows x 128 cols, full K=128.
// W converted to fp16 smem (padded rows, ldmatrix-conflict-free);
// A fragments loaded directly from gmem fp32 and converted in registers.
// ---------------------------------------------------------------------------
__global__ __launch_bounds__(128) void gemm_mma_kernel(
    const float* __restrict__ x, const float* __restrict__ W, int n)
{
    __shared__ __half ws[128][136];    // [k][n], 272B row stride

    int tid  = threadIdx.x;
    int warp = tid >> 5;
    int lane = tid & 31;

    // Load + convert W: thread t handles k-row t (32 float4 = 128 cols)
    {
        const float4* Wr = (const float4*)(W + (size_t)tid * 128);
        #pragma unroll
        for (int q = 0; q < 32; q++) {
            float4 v = Wr[q];
            *(__half2*)&ws[tid][q * 4]     = __floats2half2_rn(v.x, v.y);
            *(__half2*)&ws[tid][q * 4 + 2] = __floats2half2_rn(v.z, v.w);
        }
    }
    __syncthreads();

    int mbase = blockIdx.x * 64 + warp * 16;
    int r0 = mbase + (lane >> 2);
    int r1 = r0 + 8;
    int c0 = (lane & 3) * 2;
    bool v0 = r0 < n, v1 = r1 < n;

    float acc[16][4];
    #pragma unroll
    for (int j = 0; j < 16; j++)
        #pragma unroll
        for (int q = 0; q < 4; q++) acc[j][q] = 0.f;

    const float* xr0 = x + (size_t)(v0 ? r0 : 0) * 128;
    const float* xr1 = x + (size_t)(v1 ? r1 : 0) * 128;

    // B ldmatrix row address for this lane (within a k-chunk)
    int brow = lane & 15;

    #pragma unroll
    for (int t = 0; t < 8; t++) {
        int cb = t * 16 + c0;
        float2 f00 = v0 ? *(const float2*)(xr0 + cb)     : make_float2(0.f, 0.f);
        float2 f01 = v0 ? *(const float2*)(xr0 + cb + 8) : make_float2(0.f, 0.f);
        float2 f10 = v1 ? *(const float2*)(xr1 + cb)     : make_float2(0.f, 0.f);
        float2 f11 = v1 ? *(const float2*)(xr1 + cb + 8) : make_float2(0.f, 0.f);

        __half2 ha0 = __floats2half2_rn(f00.x, f00.y);
        __half2 ha1 = __floats2half2_rn(f10.x, f10.y);
        __half2 ha2 = __floats2half2_rn(f01.x, f01.y);
        __half2 ha3 = __floats2half2_rn(f11.x, f11.y);
        unsigned a0 = *(unsigned*)&ha0;
        unsigned a1 = *(unsigned*)&ha1;
        unsigned a2 = *(unsigned*)&ha2;
        unsigned a3 = *(unsigned*)&ha3;

        #pragma unroll
        for (int j = 0; j < 16; j++) {
            unsigned b0, b1;
            unsigned baddr = (unsigned)__cvta_generic_to_shared(
                &ws[t * 16 + brow][j * 8]);
            asm volatile(
                "ldmatrix.sync.aligned.m8n8.x2.trans.shared.b16 {%0,%1}, [%2];"
                : "=r"(b0), "=r"(b1) : "r"(baddr));
            asm volatile(
                "mma.sync.aligned.m16n8k16.row.col.f32.f16.f16.f32 "
                "{%0,%1,%2,%3}, {%4,%5,%6,%7}, {%8,%9}, {%0,%1,%2,%3};"
                : "+f"(acc[j][0]), "+f"(acc[j][1]), "+f"(acc[j][2]), "+f"(acc[j][3])
                : "r"(a0), "r"(a1), "r"(a2), "r"(a3), "r"(b0), "r"(b1));
        }
    }

    // Epilogue: d0,d1 -> row r0 cols (8j+c0, +1); d2,d3 -> row r1.
    if (v0) {
        #pragma unroll
        for (int j = 0; j < 16; j++)
            *(__half2*)&g_h[(size_t)r0 * HD + j * 8 + c0] =
                __floats2half2_rn(acc[j][0], acc[j][1]);
    }
    if (v1) {
        #pragma unroll
        for (int j = 0; j < 16; j++)
            *(__half2*)&g_h[(size_t)r1 * HD + j * 8 + c0] =
                __floats2half2_rn(acc[j][2], acc[j][3]);
    }
}

// ---------------------------------------------------------------------------
// K2: per-node attention logits from fp16 h. One warp per node.
// ---------------------------------------------------------------------------
__global__ void logits_kernel(const float* __restrict__ a_src,
                              const float* __restrict__ a_dst, int n)
{
    int gw = (blockIdx.x * blockDim.x + threadIdx.x) >> 5;
    int lane = threadIdx.x & 31;
    if (gw >= n) return;
    int hd = lane >> 3;
    int sub = lane & 7;

    uint2 raw = ((const uint2*)g_h)[(size_t)gw * 32 + lane];
    float2 f0 = __half22float2(*(__half2*)&raw.x);
    float2 f1 = __half22float2(*(__half2*)&raw.y);

    float4 as = *(const float4*)&a_src[hd * D + sub * 4];
    float4 ad = *(const float4*)&a_dst[hd * D + sub * 4];

    float s = f0.x * as.x + f0.y * as.y + f1.x * as.z + f1.y * as.w;
    float d = f0.x * ad.x + f0.y * ad.y + f1.x * ad.z + f1.y * ad.w;

    s += __shfl_down_sync(0xffffffffu, s, 4, 8);
    s += __shfl_down_sync(0xffffffffu, s, 2, 8);
    s += __shfl_down_sync(0xffffffffu, s, 1, 8);
    d += __shfl_down_sync(0xffffffffu, d, 4, 8);
    d += __shfl_down_sync(0xffffffffu, d, 2, 8);
    d += __shfl_down_sync(0xffffffffu, d, 1, 8);

    if (sub == 0) {
        g_es[gw * H + hd] = s;
        g_ed[gw * H + hd] = d;
    }
}

// ---------------------------------------------------------------------------
// K3: in-degree histogram
// ---------------------------------------------------------------------------
__global__ void hist_kernel(const void* __restrict__ edge_dst, int e) {
    int i = blockIdx.x * blockDim.x + threadIdx.x;
    if (i < e) atomicAdd(&g_count[edge_at(edge_dst, i)], 1);
}

// ---------------------------------------------------------------------------
// K4: single-block exclusive scan over counts -> rowstart + cursors
// ---------------------------------------------------------------------------
__global__ void scan_kernel(int n) {
    __shared__ int part[1024];
    int t = threadIdx.x;
    int per = (n + 1023) / 1024;
    int s = t * per;
    int e = min(s + per, n);

    int sum = 0;
    for (int i = s; i < e; i++) sum += g_count[i];
    part[t] = sum;
    __syncthreads();

    for (int off = 1; off < 1024; off <<= 1) {
        int v = (t >= off) ? part[t - off] : 0;
        __syncthreads();
        part[t] += v;
        __syncthreads();
    }

    int base = (t == 0) ? 0 : part[t - 1];
    for (int i = s; i < e; i++) {
        g_rowstart[i] = base;
        g_cursor[i]   = base;
        base += g_count[i];
    }
    if (t == 1023) g_rowstart[n] = part[1023];
}

// ---------------------------------------------------------------------------
// K5: scatter edges into dst-grouped order
// ---------------------------------------------------------------------------
__global__ void scatter_kernel(const void* __restrict__ edge_src,
                               const void* __restrict__ edge_dst, int e)
{
    int i = blockIdx.x * blockDim.x + threadIdx.x;
    if (i >= e) return;
    int dst = edge_at(edge_dst, i);
    int pos = atomicAdd(&g_cursor[dst], 1);
    g_srcsorted[pos] = edge_at(edge_src, i);
}

// ---------------------------------------------------------------------------
// K6: aggregation. One warp per destination node, fp32 accumulators over
// fp16 gathered rows, no output atomics.
// ---------------------------------------------------------------------------
__global__ void agg_kernel(const float* __restrict__ bias,
                           float* __restrict__ out, int n)
{
    int gw = (blockIdx.x * blockDim.x + threadIdx.x) >> 5;
    int lane = threadIdx.x & 31;
    if (gw >= n) return;
    int hd = lane >> 3;

    float edv = g_ed[gw * H + hd];
    int start = g_rowstart[gw];
    int end   = g_rowstart[gw + 1];

    float4 acc = make_float4(0.f, 0.f, 0.f, 0.f);
    float denom = 0.f;
    const uint2* h2 = (const uint2*)g_h;

    #pragma unroll 4
    for (int i = start; i < end; ++i) {
        int src = g_srcsorted[i];
        float ev = g_es[src * H + hd] + edv;
        ev = fmaxf(ev, 0.2f * ev);          // LeakyReLU(0.2)
        float al = __expf(ev);
        denom += al;
        uint2 raw = h2[(size_t)src * 32 + lane];
        float2 f0 = __half22float2(*(__half2*)&raw.x);
        float2 f1 = __half22float2(*(__half2*)&raw.y);
        acc.x = fmaf(al, f0.x, acc.x);
        acc.y = fmaf(al, f0.y, acc.y);
        acc.z = fmaf(al, f1.x, acc.z);
        acc.w = fmaf(al, f1.y, acc.w);
    }

    float inv = denom > 0.f ? 1.0f / denom : 0.f;
    float4 bv = ((const float4*)bias)[lane];
    float4 o;
    o.x = fmaf(acc.x, inv, bv.x);
    o.y = fmaf(acc.y, inv, bv.y);
    o.z = fmaf(acc.z, inv, bv.z);
    o.w = fmaf(acc.w, inv, bv.w);
    ((float4*)out)[(size_t)gw * 32 + lane] = o;
}

// ---------------------------------------------------------------------------
extern "C" void kernel_launch(void* const* d_in, const int* in_sizes, int n_in,
                              void* d_out, int out_size)
{
    const float* x      = (const float*)d_in[0];
    const float* W      = (const float*)d_in[1];
    const float* a_src  = (const float*)d_in[2];
    const float* a_dst  = (const float*)d_in[3];
    const float* bias   = (const float*)d_in[4];
    const void*  esrc   = d_in[5];
    const void*  edst   = d_in[6];
    float* out = (float*)d_out;

    int n = in_sizes[0] / F;     // 50000
    int e = in_sizes[5];         // 1600000

    zero_kernel<<<(n + 255) / 256, 256>>>(n, edst);
    gemm_mma_kernel<<<(n + 63) / 64, 128>>>(x, W, n);
    logits_kernel<<<(n * 32 + 255) / 256, 256>>>(a_src, a_dst, n);
    hist_kernel<<<(e + 255) / 256, 256>>>(edst, e);
    scan_kernel<<<1, 1024>>>(n);
    scatter_kernel<<<(e + 255) / 256, 256>>>(esrc, edst, e);
    agg_kernel<<<(n * 32 + 255) / 256, 256>>>(bias, out, n);
}

// round 5
// speedup vs baseline: 1.2780x; 1.0875x over previous
#include <cuda_runtime.h>
#include <cuda_fp16.h>

#define NN 50000
#define EE 1600000
#define F  128
#define H  4
#define D  32
#define HD 128

// Scratch (allocation-free rule: __device__ globals)
__device__ __half g_h[NN * HD];         // projected features fp16, 12.8 MB (L2-resident)
__device__ float g_es[NN * H];          // per-node source logits
__device__ float g_ed[NN * H];          // per-node dest logits
__device__ int   g_count[NN];           // in-degree histogram
__device__ int   g_rowstart[NN + 1];    // CSR row offsets (by dst)
__device__ int   g_cursor[NN];          // scatter cursors
__device__ int   g_srcsorted[EE];       // src node per edge, grouped by dst
__device__ int   g_is64;                // 1 if edge arrays are int64, 0 if int32

__device__ __forceinline__ int edge_at(const void* edges, int i) {
    if (g_is64) return (int)((const long long*)edges)[i];
    return ((const int*)edges)[i];
}

// ---------------------------------------------------------------------------
// K0: zero the histogram + detect edge dtype
// ---------------------------------------------------------------------------
__global__ void zero_kernel(int n, const void* edges) {
    int i = blockIdx.x * blockDim.x + threadIdx.x;
    if (i < n) g_count[i] = 0;
    if (i == 0) {
        const long long* p = (const long long*)edges;
        int ok = 1;
        #pragma unroll
        for (int q = 0; q < 8; q++) {
            long long v = p[q];
            if (v < 0 || v >= NN) ok = 0;
        }
        g_is64 = ok;
    }
}

// ---------------------------------------------------------------------------
// K1: h = x @ W via HMMA + fused per-node logits epilogue.
// 256 threads (8 warps), tile 128 rows x 128 cols, full K=128.
// ---------------------------------------------------------------------------
__global__ __launch_bounds__(256) void gemm_mma_kernel(
    const float* __restrict__ x, const float* __restrict__ W,
    const float* __restrict__ a_src, const float* __restrict__ a_dst, int n)
{
    __shared__ __half ws[128][136];    // [k][n], 272B row stride
    __shared__ float as_s[128];
    __shared__ float ad_s[128];

    int tid  = threadIdx.x;
    int warp = tid >> 5;
    int lane = tid & 31;

    // Coalesced W load+convert: linear float4 partition.
    {
        const float4* W4 = (const float4*)W;
        #pragma unroll
        for (int q = 0; q < 16; q++) {
            int linear = q * 256 + tid;      // float4 index, 0..4095
            int row = linear >> 5;
            int c4  = linear & 31;
            float4 v = W4[linear];
            *(__half2*)&ws[row][c4 * 4]     = __floats2half2_rn(v.x, v.y);
            *(__half2*)&ws[row][c4 * 4 + 2] = __floats2half2_rn(v.z, v.w);
        }
        if (tid < 128) as_s[tid] = a_src[tid];
        else           ad_s[tid - 128] = a_dst[tid - 128];
    }
    __syncthreads();

    int mbase = blockIdx.x * 128 + warp * 16;
    int r0 = mbase + (lane >> 2);
    int r1 = r0 + 8;
    int c0 = (lane & 3) * 2;
    bool v0 = r0 < n, v1 = r1 < n;

    float acc[16][4];
    #pragma unroll
    for (int j = 0; j < 16; j++)
        #pragma unroll
        for (int q = 0; q < 4; q++) acc[j][q] = 0.f;

    const float* xr0 = x + (size_t)(v0 ? r0 : 0) * 128;
    const float* xr1 = x + (size_t)(v1 ? r1 : 0) * 128;
    int brow = lane & 15;

    #pragma unroll
    for (int t = 0; t < 8; t++) {
        int cb = t * 16 + c0;
        float2 f00 = v0 ? *(const float2*)(xr0 + cb)     : make_float2(0.f, 0.f);
        float2 f01 = v0 ? *(const float2*)(xr0 + cb + 8) : make_float2(0.f, 0.f);
        float2 f10 = v1 ? *(const float2*)(xr1 + cb)     : make_float2(0.f, 0.f);
        float2 f11 = v1 ? *(const float2*)(xr1 + cb + 8) : make_float2(0.f, 0.f);

        __half2 ha0 = __floats2half2_rn(f00.x, f00.y);
        __half2 ha1 = __floats2half2_rn(f10.x, f10.y);
        __half2 ha2 = __floats2half2_rn(f01.x, f01.y);
        __half2 ha3 = __floats2half2_rn(f11.x, f11.y);
        unsigned a0 = *(unsigned*)&ha0;
        unsigned a1 = *(unsigned*)&ha1;
        unsigned a2 = *(unsigned*)&ha2;
        unsigned a3 = *(unsigned*)&ha3;

        #pragma unroll
        for (int j = 0; j < 16; j++) {
            unsigned b0, b1;
            unsigned baddr = (unsigned)__cvta_generic_to_shared(
                &ws[t * 16 + brow][j * 8]);
            asm volatile(
                "ldmatrix.sync.aligned.m8n8.x2.trans.shared.b16 {%0,%1}, [%2];"
                : "=r"(b0), "=r"(b1) : "r"(baddr));
            asm volatile(
                "mma.sync.aligned.m16n8k16.row.col.f32.f16.f16.f32 "
                "{%0,%1,%2,%3}, {%4,%5,%6,%7}, {%8,%9}, {%0,%1,%2,%3};"
                : "+f"(acc[j][0]), "+f"(acc[j][1]), "+f"(acc[j][2]), "+f"(acc[j][3])
                : "r"(a0), "r"(a1), "r"(a2), "r"(a3), "r"(b0), "r"(b1));
        }
    }

    // h epilogue (fp16 store)
    if (v0) {
        #pragma unroll
        for (int j = 0; j < 16; j++)
            *(__half2*)&g_h[(size_t)r0 * HD + j * 8 + c0] =
                __floats2half2_rn(acc[j][0], acc[j][1]);
    }
    if (v1) {
        #pragma unroll
        for (int j = 0; j < 16; j++)
            *(__half2*)&g_h[(size_t)r1 * HD + j * 8 + c0] =
                __floats2half2_rn(acc[j][2], acc[j][3]);
    }

    // Fused logits: per-head dot of row accs with a_src / a_dst.
    // Head hd covers cols 32*hd..32*hd+31 == j in [4hd, 4hd+4).
    float4 es0 = make_float4(0,0,0,0), ed0 = es0, es1 = es0, ed1 = es0;
    #pragma unroll
    for (int hd = 0; hd < 4; hd++) {
        float s0 = 0.f, d0 = 0.f, s1 = 0.f, d1 = 0.f;
        #pragma unroll
        for (int jj = 0; jj < 4; jj++) {
            int j = hd * 4 + jj;
            float wa = as_s[j * 8 + c0];
            float wb = as_s[j * 8 + c0 + 1];
            float va = ad_s[j * 8 + c0];
            float vb = ad_s[j * 8 + c0 + 1];
            s0 = fmaf(acc[j][0], wa, fmaf(acc[j][1], wb, s0));
            d0 = fmaf(acc[j][0], va, fmaf(acc[j][1], vb, d0));
            s1 = fmaf(acc[j][2], wa, fmaf(acc[j][3], wb, s1));
            d1 = fmaf(acc[j][2], va, fmaf(acc[j][3], vb, d1));
        }
        ((float*)&es0)[hd] = s0; ((float*)&ed0)[hd] = d0;
        ((float*)&es1)[hd] = s1; ((float*)&ed1)[hd] = d1;
    }
    // reduce over the 4 lanes of the quad (lane&3)
    #pragma unroll
    for (int off = 1; off <= 2; off <<= 1) {
        #pragma unroll
        for (int q = 0; q < 4; q++) {
            ((float*)&es0)[q] += __shfl_xor_sync(0xffffffffu, ((float*)&es0)[q], off);
            ((float*)&ed0)[q] += __shfl_xor_sync(0xffffffffu, ((float*)&ed0)[q], off);
            ((float*)&es1)[q] += __shfl_xor_sync(0xffffffffu, ((float*)&es1)[q], off);
            ((float*)&ed1)[q] += __shfl_xor_sync(0xffffffffu, ((float*)&ed1)[q], off);
        }
    }
    if ((lane & 3) == 0) {
        if (v0) {
            *(float4*)&g_es[r0 * H] = es0;
            *(float4*)&g_ed[r0 * H] = ed0;
        }
        if (v1) {
            *(float4*)&g_es[r1 * H] = es1;
            *(float4*)&g_ed[r1 * H] = ed1;
        }
    }
}

// ---------------------------------------------------------------------------
// K3: in-degree histogram, 4 edges per thread (vectorized loads)
// ---------------------------------------------------------------------------
__global__ void hist_kernel(const void* __restrict__ edge_dst, int e) {
    int i4 = (blockIdx.x * blockDim.x + threadIdx.x) * 4;
    if (i4 + 3 < e) {
        int d0, d1, d2, d3;
        if (g_is64) {
            longlong2 p0 = ((const longlong2*)edge_dst)[i4 >> 1];
            longlong2 p1 = ((const longlong2*)edge_dst)[(i4 >> 1) + 1];
            d0 = (int)p0.x; d1 = (int)p0.y; d2 = (int)p1.x; d3 = (int)p1.y;
        } else {
            int4 p = ((const int4*)edge_dst)[i4 >> 2];
            d0 = p.x; d1 = p.y; d2 = p.z; d3 = p.w;
        }
        atomicAdd(&g_count[d0], 1);
        atomicAdd(&g_count[d1], 1);
        atomicAdd(&g_count[d2], 1);
        atomicAdd(&g_count[d3], 1);
    } else {
        for (int i = i4; i < e; i++) atomicAdd(&g_count[edge_at(edge_dst, i)], 1);
    }
}

// ---------------------------------------------------------------------------
// K4: single-block exclusive scan over counts -> rowstart + cursors
// ---------------------------------------------------------------------------
__global__ void scan_kernel(int n) {
    __shared__ int part[1024];
    int t = threadIdx.x;
    int per = (n + 1023) / 1024;
    int s = t * per;
    int e = min(s + per, n);

    int sum = 0;
    for (int i = s; i < e; i++) sum += g_count[i];
    part[t] = sum;
    __syncthreads();

    for (int off = 1; off < 1024; off <<= 1) {
        int v = (t >= off) ? part[t - off] : 0;
        __syncthreads();
        part[t] += v;
        __syncthreads();
    }

    int base = (t == 0) ? 0 : part[t - 1];
    for (int i = s; i < e; i++) {
        g_rowstart[i] = base;
        g_cursor[i]   = base;
        base += g_count[i];
    }
    if (t == 1023) g_rowstart[n] = part[1023];
}

// ---------------------------------------------------------------------------
// K5: scatter edges into dst-grouped order, 4 edges per thread
// ---------------------------------------------------------------------------
__global__ void scatter_kernel(const void* __restrict__ edge_src,
                               const void* __restrict__ edge_dst, int e)
{
    int i4 = (blockIdx.x * blockDim.x + threadIdx.x) * 4;
    if (i4 + 3 < e) {
        int d[4], s[4];
        if (g_is64) {
            longlong2 p0 = ((const longlong2*)edge_dst)[i4 >> 1];
            longlong2 p1 = ((const longlong2*)edge_dst)[(i4 >> 1) + 1];
            d[0] = (int)p0.x; d[1] = (int)p0.y; d[2] = (int)p1.x; d[3] = (int)p1.y;
            longlong2 q0 = ((const longlong2*)edge_src)[i4 >> 1];
            longlong2 q1 = ((const longlong2*)edge_src)[(i4 >> 1) + 1];
            s[0] = (int)q0.x; s[1] = (int)q0.y; s[2] = (int)q1.x; s[3] = (int)q1.y;
        } else {
            int4 p = ((const int4*)edge_dst)[i4 >> 2];
            d[0] = p.x; d[1] = p.y; d[2] = p.z; d[3] = p.w;
            int4 q = ((const int4*)edge_src)[i4 >> 2];
            s[0] = q.x; s[1] = q.y; s[2] = q.z; s[3] = q.w;
        }
        #pragma unroll
        for (int q = 0; q < 4; q++) {
            int pos = atomicAdd(&g_cursor[d[q]], 1);
            g_srcsorted[pos] = s[q];
        }
    } else {
        for (int i = i4; i < e; i++) {
            int dst = edge_at(edge_dst, i);
            int pos = atomicAdd(&g_cursor[dst], 1);
            g_srcsorted[pos] = edge_at(edge_src, i);
        }
    }
}

// ---------------------------------------------------------------------------
// K6: aggregation. One warp per destination node, fp32 accumulators over
// fp16 gathered rows, no output atomics.
// ---------------------------------------------------------------------------
__global__ void agg_kernel(const float* __restrict__ bias,
                           float* __restrict__ out, int n)
{
    int gw = (blockIdx.x * blockDim.x + threadIdx.x) >> 5;
    int lane = threadIdx.x & 31;
    if (gw >= n) return;
    int hd = lane >> 3;

    float edv = g_ed[gw * H + hd];
    int start = g_rowstart[gw];
    int end   = g_rowstart[gw + 1];

    float4 acc = make_float4(0.f, 0.f, 0.f, 0.f);
    float denom = 0.f;
    const uint2* h2 = (const uint2*)g_h;

    #pragma unroll 8
    for (int i = start; i < end; ++i) {
        int src = g_srcsorted[i];
        float ev = g_es[src * H + hd] + edv;
        ev = fmaxf(ev, 0.2f * ev);          // LeakyReLU(0.2)
        float al = __expf(ev);
        denom += al;
        uint2 raw = h2[(size_t)src * 32 + lane];
        float2 f0 = __half22float2(*(__half2*)&raw.x);
        float2 f1 = __half22float2(*(__half2*)&raw.y);
        acc.x = fmaf(al, f0.x, acc.x);
        acc.y = fmaf(al, f0.y, acc.y);
        acc.z = fmaf(al, f1.x, acc.z);
        acc.w = fmaf(al, f1.y, acc.w);
    }

    float inv = denom > 0.f ? 1.0f / denom : 0.f;
    float4 bv = ((const float4*)bias)[lane];
    float4 o;
    o.x = fmaf(acc.x, inv, bv.x);
    o.y = fmaf(acc.y, inv, bv.y);
    o.z = fmaf(acc.z, inv, bv.z);
    o.w = fmaf(acc.w, inv, bv.w);
    ((float4*)out)[(size_t)gw * 32 + lane] = o;
}

// ---------------------------------------------------------------------------
extern "C" void kernel_launch(void* const* d_in, const int* in_sizes, int n_in,
                              void* d_out, int out_size)
{
    const float* x      = (const float*)d_in[0];
    const float* W      = (const float*)d_in[1];
    const float* a_src  = (const float*)d_in[2];
    const float* a_dst  = (const float*)d_in[3];
    const float* bias   = (const float*)d_in[4];
    const void*  esrc   = d_in[5];
    const void*  edst   = d_in[6];
    float* out = (float*)d_out;

    int n = in_sizes[0] / F;     // 50000
    int e = in_sizes[5];         // 1600000

    zero_kernel<<<(n + 255) / 256, 256>>>(n, edst);
    gemm_mma_kernel<<<(n + 127) / 128, 256>>>(x, W, a_src, a_dst, n);
    hist_kernel<<<(e / 4 + 255) / 256, 256>>>(edst, e);
    scan_kernel<<<1, 1024>>>(n);
    scatter_kernel<<<(e / 4 + 255) / 256, 256>>>(esrc, edst, e);
    agg_kernel<<<(n * 32 + 255) / 256, 256>>>(bias, out, n);
}

// round 6
// speedup vs baseline: 2.0695x; 1.6193x over previous
#include <cuda_runtime.h>
#include <cuda_fp16.h>

#define NN 50000
#define EE 1600000
#define F  128
#define H  4
#define D  32
#define HD 128

#define SCAN_BLK 256
#define SCAN_NB  ((NN + SCAN_BLK - 1) / SCAN_BLK)   // 196

// Scratch (allocation-free rule: __device__ globals)
__device__ __half g_h[NN * HD];         // projected features fp16, 12.8 MB (L2-resident)
__device__ float g_es[NN * H];          // per-node source logits
__device__ float g_ed[NN * H];          // per-node dest logits
__device__ int   g_count[NN];           // in-degree histogram
__device__ int   g_rowstart[NN + 1];    // CSR row offsets (by dst)
__device__ int   g_cursor[NN];          // scatter cursors
__device__ int   g_srcsorted[EE];       // src node per edge, grouped by dst
__device__ int   g_is64;                // 1 if edge arrays are int64, 0 if int32
__device__ int   g_bsum[SCAN_NB];       // per-block partial sums
__device__ int   g_boff[SCAN_NB];       // exclusive-scanned block offsets

__device__ __forceinline__ int edge_at(const void* edges, int i) {
    if (g_is64) return (int)((const long long*)edges)[i];
    return ((const int*)edges)[i];
}

// ---------------------------------------------------------------------------
// K0: zero the histogram + detect edge dtype
// ---------------------------------------------------------------------------
__global__ void zero_kernel(int n, const void* edges) {
    int i = blockIdx.x * blockDim.x + threadIdx.x;
    if (i < n) g_count[i] = 0;
    if (i == 0) {
        const long long* p = (const long long*)edges;
        int ok = 1;
        #pragma unroll
        for (int q = 0; q < 8; q++) {
            long long v = p[q];
            if (v < 0 || v >= NN) ok = 0;
        }
        g_is64 = ok;
    }
}

// ---------------------------------------------------------------------------
// K1: h = x @ W via HMMA + fused per-node logits epilogue.
// 256 threads (8 warps), tile 128 rows x 128 cols, full K=128.
// ---------------------------------------------------------------------------
__global__ __launch_bounds__(256) void gemm_mma_kernel(
    const float* __restrict__ x, const float* __restrict__ W,
    const float* __restrict__ a_src, const float* __restrict__ a_dst, int n)
{
    __shared__ __half ws[128][136];    // [k][n], 272B row stride
    __shared__ float as_s[128];
    __shared__ float ad_s[128];

    int tid  = threadIdx.x;
    int warp = tid >> 5;
    int lane = tid & 31;

    // Coalesced W load+convert: linear float4 partition.
    {
        const float4* W4 = (const float4*)W;
        #pragma unroll
        for (int q = 0; q < 16; q++) {
            int linear = q * 256 + tid;      // float4 index, 0..4095
            int row = linear >> 5;
            int c4  = linear & 31;
            float4 v = W4[linear];
            *(__half2*)&ws[row][c4 * 4]     = __floats2half2_rn(v.x, v.y);
            *(__half2*)&ws[row][c4 * 4 + 2] = __floats2half2_rn(v.z, v.w);
        }
        if (tid < 128) as_s[tid] = a_src[tid];
        else           ad_s[tid - 128] = a_dst[tid - 128];
    }
    __syncthreads();

    int mbase = blockIdx.x * 128 + warp * 16;
    int r0 = mbase + (lane >> 2);
    int r1 = r0 + 8;
    int c0 = (lane & 3) * 2;
    bool v0 = r0 < n, v1 = r1 < n;

    float acc[16][4];
    #pragma unroll
    for (int j = 0; j < 16; j++)
        #pragma unroll
        for (int q = 0; q < 4; q++) acc[j][q] = 0.f;

    const float* xr0 = x + (size_t)(v0 ? r0 : 0) * 128;
    const float* xr1 = x + (size_t)(v1 ? r1 : 0) * 128;
    int brow = lane & 15;

    #pragma unroll
    for (int t = 0; t < 8; t++) {
        int cb = t * 16 + c0;
        float2 f00 = v0 ? *(const float2*)(xr0 + cb)     : make_float2(0.f, 0.f);
        float2 f01 = v0 ? *(const float2*)(xr0 + cb + 8) : make_float2(0.f, 0.f);
        float2 f10 = v1 ? *(const float2*)(xr1 + cb)     : make_float2(0.f, 0.f);
        float2 f11 = v1 ? *(const float2*)(xr1 + cb + 8) : make_float2(0.f, 0.f);

        __half2 ha0 = __floats2half2_rn(f00.x, f00.y);
        __half2 ha1 = __floats2half2_rn(f10.x, f10.y);
        __half2 ha2 = __floats2half2_rn(f01.x, f01.y);
        __half2 ha3 = __floats2half2_rn(f11.x, f11.y);
        unsigned a0 = *(unsigned*)&ha0;
        unsigned a1 = *(unsigned*)&ha1;
        unsigned a2 = *(unsigned*)&ha2;
        unsigned a3 = *(unsigned*)&ha3;

        #pragma unroll
        for (int j = 0; j < 16; j++) {
            unsigned b0, b1;
            unsigned baddr = (unsigned)__cvta_generic_to_shared(
                &ws[t * 16 + brow][j * 8]);
            asm volatile(
                "ldmatrix.sync.aligned.m8n8.x2.trans.shared.b16 {%0,%1}, [%2];"
                : "=r"(b0), "=r"(b1) : "r"(baddr));
            asm volatile(
                "mma.sync.aligned.m16n8k16.row.col.f32.f16.f16.f32 "
                "{%0,%1,%2,%3}, {%4,%5,%6,%7}, {%8,%9}, {%0,%1,%2,%3};"
                : "+f"(acc[j][0]), "+f"(acc[j][1]), "+f"(acc[j][2]), "+f"(acc[j][3])
                : "r"(a0), "r"(a1), "r"(a2), "r"(a3), "r"(b0), "r"(b1));
        }
    }

    // h epilogue (fp16 store)
    if (v0) {
        #pragma unroll
        for (int j = 0; j < 16; j++)
            *(__half2*)&g_h[(size_t)r0 * HD + j * 8 + c0] =
                __floats2half2_rn(acc[j][0], acc[j][1]);
    }
    if (v1) {
        #pragma unroll
        for (int j = 0; j < 16; j++)
            *(__half2*)&g_h[(size_t)r1 * HD + j * 8 + c0] =
                __floats2half2_rn(acc[j][2], acc[j][3]);
    }

    // Fused logits: per-head dot of row accs with a_src / a_dst.
    float4 es0 = make_float4(0,0,0,0), ed0 = es0, es1 = es0, ed1 = es0;
    #pragma unroll
    for (int hd = 0; hd < 4; hd++) {
        float s0 = 0.f, d0 = 0.f, s1 = 0.f, d1 = 0.f;
        #pragma unroll
        for (int jj = 0; jj < 4; jj++) {
            int j = hd * 4 + jj;
            float wa = as_s[j * 8 + c0];
            float wb = as_s[j * 8 + c0 + 1];
            float va = ad_s[j * 8 + c0];
            float vb = ad_s[j * 8 + c0 + 1];
            s0 = fmaf(acc[j][0], wa, fmaf(acc[j][1], wb, s0));
            d0 = fmaf(acc[j][0], va, fmaf(acc[j][1], vb, d0));
            s1 = fmaf(acc[j][2], wa, fmaf(acc[j][3], wb, s1));
            d1 = fmaf(acc[j][2], va, fmaf(acc[j][3], vb, d1));
        }
        ((float*)&es0)[hd] = s0; ((float*)&ed0)[hd] = d0;
        ((float*)&es1)[hd] = s1; ((float*)&ed1)[hd] = d1;
    }
    #pragma unroll
    for (int off = 1; off <= 2; off <<= 1) {
        #pragma unroll
        for (int q = 0; q < 4; q++) {
            ((float*)&es0)[q] += __shfl_xor_sync(0xffffffffu, ((float*)&es0)[q], off);
            ((float*)&ed0)[q] += __shfl_xor_sync(0xffffffffu, ((float*)&ed0)[q], off);
            ((float*)&es1)[q] += __shfl_xor_sync(0xffffffffu, ((float*)&es1)[q], off);
            ((float*)&ed1)[q] += __shfl_xor_sync(0xffffffffu, ((float*)&ed1)[q], off);
        }
    }
    if ((lane & 3) == 0) {
        if (v0) {
            *(float4*)&g_es[r0 * H] = es0;
            *(float4*)&g_ed[r0 * H] = ed0;
        }
        if (v1) {
            *(float4*)&g_es[r1 * H] = es1;
            *(float4*)&g_ed[r1 * H] = ed1;
        }
    }
}

// ---------------------------------------------------------------------------
// K3: in-degree histogram, 4 edges per thread (vectorized loads)
// ---------------------------------------------------------------------------
__global__ void hist_kernel(const void* __restrict__ edge_dst, int e) {
    int i4 = (blockIdx.x * blockDim.x + threadIdx.x) * 4;
    if (i4 + 3 < e) {
        int d0, d1, d2, d3;
        if (g_is64) {
            longlong2 p0 = ((const longlong2*)edge_dst)[i4 >> 1];
            longlong2 p1 = ((const longlong2*)edge_dst)[(i4 >> 1) + 1];
            d0 = (int)p0.x; d1 = (int)p0.y; d2 = (int)p1.x; d3 = (int)p1.y;
        } else {
            int4 p = ((const int4*)edge_dst)[i4 >> 2];
            d0 = p.x; d1 = p.y; d2 = p.z; d3 = p.w;
        }
        atomicAdd(&g_count[d0], 1);
        atomicAdd(&g_count[d1], 1);
        atomicAdd(&g_count[d2], 1);
        atomicAdd(&g_count[d3], 1);
    } else {
        for (int i = i4; i < e; i++) atomicAdd(&g_count[edge_at(edge_dst, i)], 1);
    }
}

// ---------------------------------------------------------------------------
// K4a: per-block partial sums of counts
// ---------------------------------------------------------------------------
__global__ __launch_bounds__(SCAN_BLK) void scan_partial(int n) {
    __shared__ int red[8];
    int i = blockIdx.x * SCAN_BLK + threadIdx.x;
    int v = (i < n) ? g_count[i] : 0;
    #pragma unroll
    for (int off = 16; off >= 1; off >>= 1)
        v += __shfl_down_sync(0xffffffffu, v, off);
    if ((threadIdx.x & 31) == 0) red[threadIdx.x >> 5] = v;
    __syncthreads();
    if (threadIdx.x == 0) {
        int s = 0;
        #pragma unroll
        for (int q = 0; q < 8; q++) s += red[q];
        g_bsum[blockIdx.x] = s;
    }
}

// ---------------------------------------------------------------------------
// K4b: one block exclusive-scans the block sums
// ---------------------------------------------------------------------------
__global__ __launch_bounds__(SCAN_BLK) void scan_blocksums(int nb, int n) {
    __shared__ int sh[SCAN_BLK];
    int t = threadIdx.x;
    int v = (t < nb) ? g_bsum[t] : 0;
    sh[t] = v;
    __syncthreads();
    #pragma unroll
    for (int off = 1; off < SCAN_BLK; off <<= 1) {
        int w = (t >= off) ? sh[t - off] : 0;
        __syncthreads();
        sh[t] += w;
        __syncthreads();
    }
    if (t < nb) g_boff[t] = sh[t] - v;       // exclusive
    if (t == nb - 1) g_rowstart[n] = sh[t];  // total edge count
}

// ---------------------------------------------------------------------------
// K4c: per-block exclusive scan + offset -> rowstart, cursor
// ---------------------------------------------------------------------------
__global__ __launch_bounds__(SCAN_BLK) void scan_final(int n) {
    __shared__ int sh[SCAN_BLK];
    int t = threadIdx.x;
    int i = blockIdx.x * SCAN_BLK + t;
    int v = (i < n) ? g_count[i] : 0;
    sh[t] = v;
    __syncthreads();
    #pragma unroll
    for (int off = 1; off < SCAN_BLK; off <<= 1) {
        int w = (t >= off) ? sh[t - off] : 0;
        __syncthreads();
        sh[t] += w;
        __syncthreads();
    }
    if (i < n) {
        int val = g_boff[blockIdx.x] + sh[t] - v;  // exclusive prefix
        g_rowstart[i] = val;
        g_cursor[i]   = val;
    }
}

// ---------------------------------------------------------------------------
// K5: scatter edges into dst-grouped order, 4 edges per thread
// ---------------------------------------------------------------------------
__global__ void scatter_kernel(const void* __restrict__ edge_src,
                               const void* __restrict__ edge_dst, int e)
{
    int i4 = (blockIdx.x * blockDim.x + threadIdx.x) * 4;
    if (i4 + 3 < e) {
        int d[4], s[4];
        if (g_is64) {
            longlong2 p0 = ((const longlong2*)edge_dst)[i4 >> 1];
            longlong2 p1 = ((const longlong2*)edge_dst)[(i4 >> 1) + 1];
            d[0] = (int)p0.x; d[1] = (int)p0.y; d[2] = (int)p1.x; d[3] = (int)p1.y;
            longlong2 q0 = ((const longlong2*)edge_src)[i4 >> 1];
            longlong2 q1 = ((const longlong2*)edge_src)[(i4 >> 1) + 1];
            s[0] = (int)q0.x; s[1] = (int)q0.y; s[2] = (int)q1.x; s[3] = (int)q1.y;
        } else {
            int4 p = ((const int4*)edge_dst)[i4 >> 2];
            d[0] = p.x; d[1] = p.y; d[2] = p.z; d[3] = p.w;
            int4 q = ((const int4*)edge_src)[i4 >> 2];
            s[0] = q.x; s[1] = q.y; s[2] = q.z; s[3] = q.w;
        }
        #pragma unroll
        for (int q = 0; q < 4; q++) {
            int pos = atomicAdd(&g_cursor[d[q]], 1);
            g_srcsorted[pos] = s[q];
        }
    } else {
        for (int i = i4; i < e; i++) {
            int dst = edge_at(edge_dst, i);
            int pos = atomicAdd(&g_cursor[dst], 1);
            g_srcsorted[pos] = edge_at(edge_src, i);
        }
    }
}

// ---------------------------------------------------------------------------
// K6: aggregation. One warp per destination node, fp32 accumulators over
// fp16 gathered rows, no output atomics.
// ---------------------------------------------------------------------------
__global__ void agg_kernel(const float* __restrict__ bias,
                           float* __restrict__ out, int n)
{
    int gw = (blockIdx.x * blockDim.x + threadIdx.x) >> 5;
    int lane = threadIdx.x & 31;
    if (gw >= n) return;
    int hd = lane >> 3;

    float edv = g_ed[gw * H + hd];
    int start = g_rowstart[gw];
    int end   = g_rowstart[gw + 1];

    float4 acc = make_float4(0.f, 0.f, 0.f, 0.f);
    float denom = 0.f;
    const uint2* h2 = (const uint2*)g_h;

    #pragma unroll 8
    for (int i = start; i < end; ++i) {
        int src = g_srcsorted[i];
        float ev = g_es[src * H + hd] + edv;
        ev = fmaxf(ev, 0.2f * ev);          // LeakyReLU(0.2)
        float al = __expf(ev);
        denom += al;
        uint2 raw = h2[(size_t)src * 32 + lane];
        float2 f0 = __half22float2(*(__half2*)&raw.x);
        float2 f1 = __half22float2(*(__half2*)&raw.y);
        acc.x = fmaf(al, f0.x, acc.x);
        acc.y = fmaf(al, f0.y, acc.y);
        acc.z = fmaf(al, f1.x, acc.z);
        acc.w = fmaf(al, f1.y, acc.w);
    }

    float inv = denom > 0.f ? 1.0f / denom : 0.f;
    float4 bv = ((const float4*)bias)[lane];
    float4 o;
    o.x = fmaf(acc.x, inv, bv.x);
    o.y = fmaf(acc.y, inv, bv.y);
    o.z = fmaf(acc.z, inv, bv.z);
    o.w = fmaf(acc.w, inv, bv.w);
    ((float4*)out)[(size_t)gw * 32 + lane] = o;
}

// ---------------------------------------------------------------------------
extern "C" void kernel_launch(void* const* d_in, const int* in_sizes, int n_in,
                              void* d_out, int out_size)
{
    const float* x      = (const float*)d_in[0];
    const float* W      = (const float*)d_in[1];
    const float* a_src  = (const float*)d_in[2];
    const float* a_dst  = (const float*)d_in[3];
    const float* bias   = (const float*)d_in[4];
    const void*  esrc   = d_in[5];
    const void*  edst   = d_in[6];
    float* out = (float*)d_out;

    int n = in_sizes[0] / F;     // 50000
    int e = in_sizes[5];         // 1600000
    int nb = (n + SCAN_BLK - 1) / SCAN_BLK;

    zero_kernel<<<(n + 255) / 256, 256>>>(n, edst);
    gemm_mma_kernel<<<(n + 127) / 128, 256>>>(x, W, a_src, a_dst, n);
    hist_kernel<<<(e / 4 + 255) / 256, 256>>>(edst, e);
    scan_partial<<<nb, SCAN_BLK>>>(n);
    scan_blocksums<<<1, SCAN_BLK>>>(nb, n);
    scan_final<<<nb, SCAN_BLK>>>(n);
    scatter_kernel<<<(e / 4 + 255) / 256, 256>>>(esrc, edst, e);
    agg_kernel<<<(n * 32 + 255) / 256, 256>>>(bias, out, n);
}

// round 7
// speedup vs baseline: 2.1854x; 1.0560x over previous
#include <cuda_runtime.h>
#include <cuda_fp16.h>

#define NN 50000
#define EE 1600000
#define F  128
#define H  4
#define D  32
#define HD 128

#define SCAN_BLK 256
#define SCAN_NB  ((NN + SCAN_BLK - 1) / SCAN_BLK)   // 196

// Scratch (allocation-free rule: __device__ globals)
__device__ __half g_h[NN * HD];         // projected features fp16, 12.8 MB (L2-resident)
__device__ float g_es[NN * H];          // per-node source logits
__device__ float g_ed[NN * H];          // per-node dest logits
__device__ int   g_count[NN];           // in-degree histogram
__device__ int   g_rowstart[NN + 1];    // CSR row offsets (by dst)
__device__ int   g_cursor[NN];          // scatter cursors
__device__ int   g_srcsorted[EE];       // src node per edge, grouped by dst
__device__ int   g_is64;                // 1 if edge arrays are int64, 0 if int32
__device__ int   g_bsum[SCAN_NB];       // per-block partial sums

__device__ __forceinline__ int edge_at(const void* edges, int i) {
    if (g_is64) return (int)((const long long*)edges)[i];
    return ((const int*)edges)[i];
}

// ---------------------------------------------------------------------------
// K0: zero the histogram + detect edge dtype
// ---------------------------------------------------------------------------
__global__ void zero_kernel(int n, const void* edges) {
    int i = blockIdx.x * blockDim.x + threadIdx.x;
    if (i < n) g_count[i] = 0;
    if (i == 0) {
        const long long* p = (const long long*)edges;
        int ok = 1;
        #pragma unroll
        for (int q = 0; q < 8; q++) {
            long long v = p[q];
            if (v < 0 || v >= NN) ok = 0;
        }
        g_is64 = ok;
    }
}

// ---------------------------------------------------------------------------
// K1: HYBRID kernel. Blocks [0, gemm_blocks): HMMA GEMM + fused logits.
//     Blocks [gemm_blocks, ...): in-degree histogram (overlaps under GEMM —
//     disjoint pipes: tensor/FMA vs L2-atomic latency).
// ---------------------------------------------------------------------------
__global__ __launch_bounds__(256) void gemm_hist_kernel(
    const float* __restrict__ x, const float* __restrict__ W,
    const float* __restrict__ a_src, const float* __restrict__ a_dst, int n,
    const void* __restrict__ edge_dst, int e, int gemm_blocks)
{
    __shared__ __half ws[128][136];    // [k][n], 272B row stride
    __shared__ float as_s[128];
    __shared__ float ad_s[128];

    int tid = threadIdx.x;

    if (blockIdx.x >= gemm_blocks) {
        // ----- histogram part: 4 edges per thread, vectorized loads -----
        int hb = blockIdx.x - gemm_blocks;
        int i4 = (hb * 256 + tid) * 4;
        if (i4 + 3 < e) {
            int d0, d1, d2, d3;
            if (g_is64) {
                longlong2 p0 = ((const longlong2*)edge_dst)[i4 >> 1];
                longlong2 p1 = ((const longlong2*)edge_dst)[(i4 >> 1) + 1];
                d0 = (int)p0.x; d1 = (int)p0.y; d2 = (int)p1.x; d3 = (int)p1.y;
            } else {
                int4 p = ((const int4*)edge_dst)[i4 >> 2];
                d0 = p.x; d1 = p.y; d2 = p.z; d3 = p.w;
            }
            atomicAdd(&g_count[d0], 1);
            atomicAdd(&g_count[d1], 1);
            atomicAdd(&g_count[d2], 1);
            atomicAdd(&g_count[d3], 1);
        } else {
            for (int i = i4; i < e; i++) atomicAdd(&g_count[edge_at(edge_dst, i)], 1);
        }
        return;
    }

    // ----- GEMM part -----
    int warp = tid >> 5;
    int lane = tid & 31;

    // Coalesced W load+convert: linear float4 partition.
    {
        const float4* W4 = (const float4*)W;
        #pragma unroll
        for (int q = 0; q < 16; q++) {
            int linear = q * 256 + tid;      // float4 index, 0..4095
            int row = linear >> 5;
            int c4  = linear & 31;
            float4 v = W4[linear];
            *(__half2*)&ws[row][c4 * 4]     = __floats2half2_rn(v.x, v.y);
            *(__half2*)&ws[row][c4 * 4 + 2] = __floats2half2_rn(v.z, v.w);
        }
        if (tid < 128) as_s[tid] = a_src[tid];
        else           ad_s[tid - 128] = a_dst[tid - 128];
    }
    __syncthreads();

    int mbase = blockIdx.x * 128 + warp * 16;
    int r0 = mbase + (lane >> 2);
    int r1 = r0 + 8;
    int c0 = (lane & 3) * 2;
    bool v0 = r0 < n, v1 = r1 < n;

    float acc[16][4];
    #pragma unroll
    for (int j = 0; j < 16; j++)
        #pragma unroll
        for (int q = 0; q < 4; q++) acc[j][q] = 0.f;

    const float* xr0 = x + (size_t)(v0 ? r0 : 0) * 128;
    const float* xr1 = x + (size_t)(v1 ? r1 : 0) * 128;
    int brow = lane & 15;

    #pragma unroll
    for (int t = 0; t < 8; t++) {
        int cb = t * 16 + c0;
        float2 f00 = v0 ? *(const float2*)(xr0 + cb)     : make_float2(0.f, 0.f);
        float2 f01 = v0 ? *(const float2*)(xr0 + cb + 8) : make_float2(0.f, 0.f);
        float2 f10 = v1 ? *(const float2*)(xr1 + cb)     : make_float2(0.f, 0.f);
        float2 f11 = v1 ? *(const float2*)(xr1 + cb + 8) : make_float2(0.f, 0.f);

        __half2 ha0 = __floats2half2_rn(f00.x, f00.y);
        __half2 ha1 = __floats2half2_rn(f10.x, f10.y);
        __half2 ha2 = __floats2half2_rn(f01.x, f01.y);
        __half2 ha3 = __floats2half2_rn(f11.x, f11.y);
        unsigned a0 = *(unsigned*)&ha0;
        unsigned a1 = *(unsigned*)&ha1;
        unsigned a2 = *(unsigned*)&ha2;
        unsigned a3 = *(unsigned*)&ha3;

        #pragma unroll
        for (int j = 0; j < 16; j++) {
            unsigned b0, b1;
            unsigned baddr = (unsigned)__cvta_generic_to_shared(
                &ws[t * 16 + brow][j * 8]);
            asm volatile(
                "ldmatrix.sync.aligned.m8n8.x2.trans.shared.b16 {%0,%1}, [%2];"
                : "=r"(b0), "=r"(b1) : "r"(baddr));
            asm volatile(
                "mma.sync.aligned.m16n8k16.row.col.f32.f16.f16.f32 "
                "{%0,%1,%2,%3}, {%4,%5,%6,%7}, {%8,%9}, {%0,%1,%2,%3};"
                : "+f"(acc[j][0]), "+f"(acc[j][1]), "+f"(acc[j][2]), "+f"(acc[j][3])
                : "r"(a0), "r"(a1), "r"(a2), "r"(a3), "r"(b0), "r"(b1));
        }
    }

    // h epilogue (fp16 store)
    if (v0) {
        #pragma unroll
        for (int j = 0; j < 16; j++)
            *(__half2*)&g_h[(size_t)r0 * HD + j * 8 + c0] =
                __floats2half2_rn(acc[j][0], acc[j][1]);
    }
    if (v1) {
        #pragma unroll
        for (int j = 0; j < 16; j++)
            *(__half2*)&g_h[(size_t)r1 * HD + j * 8 + c0] =
                __floats2half2_rn(acc[j][2], acc[j][3]);
    }

    // Fused logits: per-head dot of row accs with a_src / a_dst.
    float4 es0 = make_float4(0,0,0,0), ed0 = es0, es1 = es0, ed1 = es0;
    #pragma unroll
    for (int hd = 0; hd < 4; hd++) {
        float s0 = 0.f, d0 = 0.f, s1 = 0.f, d1 = 0.f;
        #pragma unroll
        for (int jj = 0; jj < 4; jj++) {
            int j = hd * 4 + jj;
            float wa = as_s[j * 8 + c0];
            float wb = as_s[j * 8 + c0 + 1];
            float va = ad_s[j * 8 + c0];
            float vb = ad_s[j * 8 + c0 + 1];
            s0 = fmaf(acc[j][0], wa, fmaf(acc[j][1], wb, s0));
            d0 = fmaf(acc[j][0], va, fmaf(acc[j][1], vb, d0));
            s1 = fmaf(acc[j][2], wa, fmaf(acc[j][3], wb, s1));
            d1 = fmaf(acc[j][2], va, fmaf(acc[j][3], vb, d1));
        }
        ((float*)&es0)[hd] = s0; ((float*)&ed0)[hd] = d0;
        ((float*)&es1)[hd] = s1; ((float*)&ed1)[hd] = d1;
    }
    #pragma unroll
    for (int off = 1; off <= 2; off <<= 1) {
        #pragma unroll
        for (int q = 0; q < 4; q++) {
            ((float*)&es0)[q] += __shfl_xor_sync(0xffffffffu, ((float*)&es0)[q], off);
            ((float*)&ed0)[q] += __shfl_xor_sync(0xffffffffu, ((float*)&ed0)[q], off);
            ((float*)&es1)[q] += __shfl_xor_sync(0xffffffffu, ((float*)&es1)[q], off);
            ((float*)&ed1)[q] += __shfl_xor_sync(0xffffffffu, ((float*)&ed1)[q], off);
        }
    }
    if ((lane & 3) == 0) {
        if (v0) {
            *(float4*)&g_es[r0 * H] = es0;
            *(float4*)&g_ed[r0 * H] = ed0;
        }
        if (v1) {
            *(float4*)&g_es[r1 * H] = es1;
            *(float4*)&g_ed[r1 * H] = ed1;
        }
    }
}

// ---------------------------------------------------------------------------
// K2a: per-block partial sums of counts
// ---------------------------------------------------------------------------
__global__ __launch_bounds__(SCAN_BLK) void scan_partial(int n) {
    __shared__ int red[8];
    int i = blockIdx.x * SCAN_BLK + threadIdx.x;
    int v = (i < n) ? g_count[i] : 0;
    #pragma unroll
    for (int off = 16; off >= 1; off >>= 1)
        v += __shfl_down_sync(0xffffffffu, v, off);
    if ((threadIdx.x & 31) == 0) red[threadIdx.x >> 5] = v;
    __syncthreads();
    if (threadIdx.x == 0) {
        int s = 0;
        #pragma unroll
        for (int q = 0; q < 8; q++) s += red[q];
        g_bsum[blockIdx.x] = s;
    }
}

// ---------------------------------------------------------------------------
// K2b: per-block scan; each block redundantly reduces the block sums for its
// own offset (196 loads, trivial) -> rowstart, cursor. Also writes total.
// ---------------------------------------------------------------------------
__global__ __launch_bounds__(SCAN_BLK) void scan_final(int n, int nb) {
    __shared__ int sh[SCAN_BLK];
    __shared__ int red_pref[8], red_tot[8];
    int t = threadIdx.x;

    // this block's offset = sum of bsum[j] for j < blockIdx.x; total = sum all
    int vp = (t < nb && t < blockIdx.x) ? g_bsum[t] : 0;
    int vt = (t < nb) ? g_bsum[t] : 0;
    #pragma unroll
    for (int off = 16; off >= 1; off >>= 1) {
        vp += __shfl_down_sync(0xffffffffu, vp, off);
        vt += __shfl_down_sync(0xffffffffu, vt, off);
    }
    if ((t & 31) == 0) { red_pref[t >> 5] = vp; red_tot[t >> 5] = vt; }

    int i = blockIdx.x * SCAN_BLK + t;
    int v = (i < n) ? g_count[i] : 0;
    sh[t] = v;
    __syncthreads();

    int boff = red_pref[0] + red_pref[1] + red_pref[2] + red_pref[3]
             + red_pref[4] + red_pref[5] + red_pref[6] + red_pref[7];
    int total = red_tot[0] + red_tot[1] + red_tot[2] + red_tot[3]
              + red_tot[4] + red_tot[5] + red_tot[6] + red_tot[7];

    #pragma unroll
    for (int off = 1; off < SCAN_BLK; off <<= 1) {
        int w = (t >= off) ? sh[t - off] : 0;
        __syncthreads();
        sh[t] += w;
        __syncthreads();
    }
    if (i < n) {
        int val = boff + sh[t] - v;  // exclusive prefix
        g_rowstart[i] = val;
        g_cursor[i]   = val;
        if (i == n - 1) g_rowstart[n] = total;
    }
}

// ---------------------------------------------------------------------------
// K3: scatter edges into dst-grouped order, 4 edges per thread
// ---------------------------------------------------------------------------
__global__ void scatter_kernel(const void* __restrict__ edge_src,
                               const void* __restrict__ edge_dst, int e)
{
    int i4 = (blockIdx.x * blockDim.x + threadIdx.x) * 4;
    if (i4 + 3 < e) {
        int d[4], s[4];
        if (g_is64) {
            longlong2 p0 = ((const longlong2*)edge_dst)[i4 >> 1];
            longlong2 p1 = ((const longlong2*)edge_dst)[(i4 >> 1) + 1];
            d[0] = (int)p0.x; d[1] = (int)p0.y; d[2] = (int)p1.x; d[3] = (int)p1.y;
            longlong2 q0 = ((const longlong2*)edge_src)[i4 >> 1];
            longlong2 q1 = ((const longlong2*)edge_src)[(i4 >> 1) + 1];
            s[0] = (int)q0.x; s[1] = (int)q0.y; s[2] = (int)q1.x; s[3] = (int)q1.y;
        } else {
            int4 p = ((const int4*)edge_dst)[i4 >> 2];
            d[0] = p.x; d[1] = p.y; d[2] = p.z; d[3] = p.w;
            int4 q = ((const int4*)edge_src)[i4 >> 2];
            s[0] = q.x; s[1] = q.y; s[2] = q.z; s[3] = q.w;
        }
        #pragma unroll
        for (int q = 0; q < 4; q++) {
            int pos = atomicAdd(&g_cursor[d[q]], 1);
            g_srcsorted[pos] = s[q];
        }
    } else {
        for (int i = i4; i < e; i++) {
            int dst = edge_at(edge_dst, i);
            int pos = atomicAdd(&g_cursor[dst], 1);
            g_srcsorted[pos] = edge_at(edge_src, i);
        }
    }
}

// ---------------------------------------------------------------------------
// K4: aggregation. One warp per destination node, fp32 accumulators over
// fp16 gathered rows, no output atomics.
// ---------------------------------------------------------------------------
__global__ void agg_kernel(const float* __restrict__ bias,
                           float* __restrict__ out, int n)
{
    int gw = (blockIdx.x * blockDim.x + threadIdx.x) >> 5;
    int lane = threadIdx.x & 31;
    if (gw >= n) return;
    int hd = lane >> 3;

    float edv = g_ed[gw * H + hd];
    int start = g_rowstart[gw];
    int end   = g_rowstart[gw + 1];

    float4 acc = make_float4(0.f, 0.f, 0.f, 0.f);
    float denom = 0.f;
    const uint2* h2 = (const uint2*)g_h;

    #pragma unroll 8
    for (int i = start; i < end; ++i) {
        int src = g_srcsorted[i];
        float ev = g_es[src * H + hd] + edv;
        ev = fmaxf(ev, 0.2f * ev);          // LeakyReLU(0.2)
        float al = __expf(ev);
        denom += al;
        uint2 raw = h2[(size_t)src * 32 + lane];
        float2 f0 = __half22float2(*(__half2*)&raw.x);
        float2 f1 = __half22float2(*(__half2*)&raw.y);
        acc.x = fmaf(al, f0.x, acc.x);
        acc.y = fmaf(al, f0.y, acc.y);
        acc.z = fmaf(al, f1.x, acc.z);
        acc.w = fmaf(al, f1.y, acc.w);
    }

    float inv = denom > 0.f ? 1.0f / denom : 0.f;
    float4 bv = ((const float4*)bias)[lane];
    float4 o;
    o.x = fmaf(acc.x, inv, bv.x);
    o.y = fmaf(acc.y, inv, bv.y);
    o.z = fmaf(acc.z, inv, bv.z);
    o.w = fmaf(acc.w, inv, bv.w);
    ((float4*)out)[(size_t)gw * 32 + lane] = o;
}

// ---------------------------------------------------------------------------
extern "C" void kernel_launch(void* const* d_in, const int* in_sizes, int n_in,
                              void* d_out, int out_size)
{
    const float* x      = (const float*)d_in[0];
    const float* W      = (const float*)d_in[1];
    const float* a_src  = (const float*)d_in[2];
    const float* a_dst  = (const float*)d_in[3];
    const float* bias   = (const float*)d_in[4];
    const void*  esrc   = d_in[5];
    const void*  edst   = d_in[6];
    float* out = (float*)d_out;

    int n = in_sizes[0] / F;     // 50000
    int e = in_sizes[5];         // 1600000
    int nb = (n + SCAN_BLK - 1) / SCAN_BLK;

    int gemm_blocks = (n + 127) / 128;
    int hist_blocks = (e / 4 + 255) / 256;

    zero_kernel<<<(n + 255) / 256, 256>>>(n, edst);
    gemm_hist_kernel<<<gemm_blocks + hist_blocks, 256>>>(
        x, W, a_src, a_dst, n, edst, e, gemm_blocks);
    scan_partial<<<nb, SCAN_BLK>>>(n);
    scan_final<<<nb, SCAN_BLK>>>(n, nb);
    scatter_kernel<<<(e / 4 + 255) / 256, 256>>>(esrc, edst, e);
    agg_kernel<<<(n * 32 + 255) / 256, 256>>>(bias, out, n);
}